// round 16
// baseline (speedup 1.0000x reference)
#include <cuda_runtime.h>
#include <cuda_bf16.h>
#include <cuda_fp16.h>
#include <cstdint>

#define NN     50000
#define IN_C   256
#define HID_C  128
#define OUT_C  64
#define E_MAX  800000
#define NB     ((NN + 255) / 256)   // 196 scan blocks

// ---------------- scratch ----------------
__device__ __align__(16) float g_dinv[NN];
__device__ __align__(16) int   g_degi[NN];          // zeroed at END of each call
__device__ __align__(16) int   g_row [NN + 1];
__device__ __align__(16) int   g_cur [NN];
__device__ __align__(16) unsigned long long g_desc[NB];  // zeroed at END of each call
__device__ __align__(16) int   g_csr [E_MAX];
__device__ __align__(16) __half g_h2  [NN * HID_C];
__device__ __align__(16) __half g_agg1[NN * HID_C];
__device__ __align__(16) __half g_z2  [NN * OUT_C];
__device__ __align__(16) __half g_w1h[HID_C * IN_C];   // fp16 weights, [N,K]
__device__ __align__(16) __half g_w2h[OUT_C * HID_C];

__device__ __forceinline__ uint32_t smem_u32(const void* p) {
    uint32_t a;
    asm("{ .reg .u64 t; cvta.to.shared.u64 t, %1; cvt.u32.u64 %0, t; }" : "=r"(a) : "l"(p));
    return a;
}
__device__ __forceinline__ void ldsm_x4(uint32_t (&r)[4], uint32_t saddr) {
    asm volatile("ldmatrix.sync.aligned.m8n8.x4.shared.b16 {%0,%1,%2,%3}, [%4];"
        : "=r"(r[0]), "=r"(r[1]), "=r"(r[2]), "=r"(r[3]) : "r"(saddr));
}
__device__ __forceinline__ void cp16(uint32_t saddr, const void* g) {
    asm volatile("cp.async.cg.shared.global [%0], [%1], 16;" :: "r"(saddr), "l"(g));
}

// ---------------- prep: deg histogram (x4 vectorized) + W fp16 ---------------
__global__ void prep_count_kernel(const int* __restrict__ dst, int E,
                                  const float* __restrict__ W1, const float* __restrict__ W2,
                                  int* __restrict__ degi,
                                  __half* __restrict__ w1h, __half* __restrict__ w2h) {
    const int EQ  = E / 4;
    const int W1N = IN_C * HID_C;
    const int W2N = HID_C * OUT_C;
    int idx = blockIdx.x * blockDim.x + threadIdx.x;
    if (idx < EQ) {
        int4 d4 = reinterpret_cast<const int4*>(dst)[idx];
        atomicAdd(&degi[d4.x], 1);
        atomicAdd(&degi[d4.y], 1);
        atomicAdd(&degi[d4.z], 1);
        atomicAdd(&degi[d4.w], 1);
    } else if (idx < EQ + W1N) {
        int i = idx - EQ;
        int n = i / IN_C, k = i % IN_C;
        w1h[i] = __float2half_rn(W1[(long long)k * HID_C + n]);
    } else if (idx < EQ + W1N + W2N) {
        int i = idx - EQ - W1N;
        int n = i / HID_C, k = i % HID_C;
        w2h[i] = __float2half_rn(W2[(long long)k * OUT_C + n]);
    }
}

// ---------------- single-pass scan (decoupled lookback) + dinv ---------------
__global__ void scan_kernel(const int* __restrict__ deg, unsigned long long* __restrict__ desc,
                            int* __restrict__ row, int* __restrict__ cur,
                            float* __restrict__ dinv, int n) {
    __shared__ int s[256];
    __shared__ int s_carry;
    const int bid = blockIdx.x;
    const int t   = threadIdx.x;
    const int i   = bid * 256 + t;
    int v = (i < n) ? deg[i] : 0;
    s[t] = v;
    __syncthreads();
    #pragma unroll
    for (int off = 1; off < 256; off <<= 1) {
        int u = (t >= off) ? s[t - off] : 0;
        __syncthreads();
        s[t] += u;
        __syncthreads();
    }
    int total = s[255];
    if (t == 0) {
        unsigned long long d = ((unsigned long long)(bid == 0 ? 2u : 1u) << 32)
                             | (unsigned int)total;
        atomicExch(&desc[bid], d);
        if (bid == 0) s_carry = 0;
    }
    if (bid > 0 && t < 32) {
        int carry = 0;
        int j = bid - 1;
        while (true) {
            int jj = j - t;
            unsigned long long d = 0ULL;
            if (jj >= 0) d = *((volatile unsigned long long*)&desc[jj]);
            int st  = (int)(d >> 32);
            int val = (int)(d & 0xffffffffu);
            unsigned ready = __ballot_sync(0xffffffffu, (jj < 0) || st >= 1);
            if (ready != 0xffffffffu) continue;
            unsigned pmask = __ballot_sync(0xffffffffu, (jj >= 0) && st == 2);
            if (pmask) {
                int lp = __ffs(pmask) - 1;
                int contrib = (jj >= 0 && t <= lp) ? val : 0;
                #pragma unroll
                for (int o = 16; o > 0; o >>= 1)
                    contrib += __shfl_down_sync(0xffffffffu, contrib, o);
                carry += __shfl_sync(0xffffffffu, contrib, 0);
                break;
            } else {
                int contrib = (jj >= 0) ? val : 0;
                #pragma unroll
                for (int o = 16; o > 0; o >>= 1)
                    contrib += __shfl_down_sync(0xffffffffu, contrib, o);
                carry += __shfl_sync(0xffffffffu, contrib, 0);
                j -= 32;
                if (j < 0) break;
            }
        }
        if (t == 0) {
            atomicExch(&desc[bid], (2ULL << 32) | (unsigned int)(carry + total));
            s_carry = carry;
        }
    }
    __syncthreads();
    int carry = s_carry;
    if (i < n) {
        int excl = carry + s[t] - v;
        row[i] = excl;
        cur[i] = excl;
        dinv[i] = rsqrtf((float)v + 1.0f);
        if (i == n - 1) row[n] = excl + v;
    }
}

// ---------------- slot scatter, 4 edges per thread ---------------------------
__global__ void slot_scatter_kernel(const int* __restrict__ src, const int* __restrict__ dst,
                                    int* __restrict__ cur, int* __restrict__ csr, int E) {
    int idx = blockIdx.x * blockDim.x + threadIdx.x;
    int EQ = E / 4;
    if (idx >= EQ) return;
    int4 s4 = reinterpret_cast<const int4*>(src)[idx];
    int4 d4 = reinterpret_cast<const int4*>(dst)[idx];
    int p0 = atomicAdd(&cur[d4.x], 1);
    int p1 = atomicAdd(&cur[d4.y], 1);
    int p2 = atomicAdd(&cur[d4.z], 1);
    int p3 = atomicAdd(&cur[d4.w], 1);
    csr[p0] = s4.x;
    csr[p1] = s4.y;
    csr[p2] = s4.z;
    csr[p3] = s4.w;
}

// ---------------- mma.sync fp16 helper ---------------------------------------
__device__ __forceinline__ void mma16816h(float c[4], const uint32_t a[4], const uint32_t b[2]) {
    asm volatile(
        "mma.sync.aligned.m16n8k16.row.col.f32.f16.f16.f32 "
        "{%0,%1,%2,%3}, {%4,%5,%6,%7}, {%8,%9}, {%0,%1,%2,%3};"
        : "+f"(c[0]), "+f"(c[1]), "+f"(c[2]), "+f"(c[3])
        : "r"(a[0]), "r"(a[1]), "r"(a[2]), "r"(a[3]), "r"(b[0]), "r"(b[1]));
}

// ---------------- fp16x1 HMMA GEMM, pipelined, BM=64 (3 CTAs/SM) -------------
// BM=64, BK=32, LD=40, double-buffered stages. A: reg-prefetch LDG + cvt at STS.
// B: cp.async. 8 warps = 2 m-groups(32 rows = 2x16) x 4 n-groups(BN/4).
// TRANS=false: A fp32. TRANS=true: A fp16, op(A)=relu(bias+dinv*A).
// C fp16 = dinv[r]*acc (fp32 accum).
template<int BN, int KTOT, bool TRANS>
__global__ void __launch_bounds__(256, 3)
mma_gemm(const void* __restrict__ Av,
         const __half* __restrict__ Wh,
         __half* __restrict__ C,
         const float* __restrict__ dinv, const float* __restrict__ bias, int M) {
    const int BM = 64, BK = 32, LD = 40;
    const int NCH = KTOT / BK;
    const int NW  = BN / 4;                // n-width per warp
    const int NT  = NW / 8;                // 8-wide n-tiles per warp
    const int ASZ = BM * LD * 2;
    const int BSZ = BN * LD * 2;
    const int STG = ASZ + BSZ;
    const int ACH = (BM * BK / 4) / 256;   // A quads per thread (2)
    const int BCH = (BN * BK * 2) / 16 / 256;  // B cp.async chunks per thread

    extern __shared__ __align__(16) char smem[];
    const uint32_t s0 = smem_u32(smem);

    const int tid  = threadIdx.x;
    const int wid  = tid >> 5;
    const int lane = tid & 31;
    const int g    = lane >> 2;
    const int t    = lane & 3;
    const int wm   = wid & 1;              // 2 m-groups of 32 rows
    const int wn   = wid >> 1;             // 4 n-groups of NW cols
    const int row0 = blockIdx.x * BM;

    float acc[2][NT][4];
    #pragma unroll
    for (int mt = 0; mt < 2; mt++)
        #pragma unroll
        for (int nt = 0; nt < NT; nt++)
            #pragma unroll
            for (int q = 0; q < 4; q++) acc[mt][nt][q] = 0.0f;

    // LDSM lane offsets
    const uint32_t a_lrow = (uint32_t)(lane & 15);
    const uint32_t a_lk   = (uint32_t)((lane >> 4) << 3);
    const int b_msel = lane >> 3;
    const uint32_t b_lrow = (uint32_t)((b_msel & 2) ? 8 : 0) + (uint32_t)(lane & 7);
    const uint32_t b_lk   = (uint32_t)((b_msel & 1) << 3);

    // per-thread A-fill mapping: ACH quads, row = idx>>3, k4 = (idx&7)*4
    int a_row[ACH], a_k4[ACH];
    #pragma unroll
    for (int it = 0; it < ACH; it++) {
        int idx = tid + it * 256;
        a_row[it] = idx >> 3;
        a_k4[it]  = (idx & 7) * 4;
    }

    float4 aregf[ACH];
    uint2  aregh[ACH];

    auto prefetch_A = [&](int kc) {
        #pragma unroll
        for (int it = 0; it < ACH; it++) {
            int gr = row0 + a_row[it];
            if constexpr (TRANS) {
                aregh[it] = make_uint2(0u, 0u);
                if (gr < M)
                    aregh[it] = *reinterpret_cast<const uint2*>(
                        reinterpret_cast<const __half*>(Av) + (long long)gr * KTOT + kc + a_k4[it]);
            } else {
                aregf[it] = make_float4(0.f, 0.f, 0.f, 0.f);
                if (gr < M)
                    aregf[it] = *reinterpret_cast<const float4*>(
                        reinterpret_cast<const float*>(Av) + (long long)gr * KTOT + kc + a_k4[it]);
            }
        }
    };
    auto cpasync_B = [&](int kc, int st) {
        uint32_t bb = s0 + st * STG + ASZ;
        #pragma unroll
        for (int i = 0; i < BCH; i++) {
            int cid = tid + i * 256;
            int n   = cid >> 2;
            int k8  = (cid & 3) * 8;
            cp16(bb + (n * LD + k8) * 2, Wh + (long long)n * KTOT + kc + k8);
        }
        asm volatile("cp.async.commit_group;");
    };
    auto sts_A = [&](int kc, int st) {
        __half* as = reinterpret_cast<__half*>(smem + st * STG);
        #pragma unroll
        for (int it = 0; it < ACH; it++) {
            float4 v;
            if constexpr (TRANS) {
                int gr = row0 + a_row[it];
                float2 f0 = __half22float2(*reinterpret_cast<__half2*>(&aregh[it].x));
                float2 f1 = __half22float2(*reinterpret_cast<__half2*>(&aregh[it].y));
                float di = (gr < M) ? dinv[gr] : 0.0f;
                float4 bb = *reinterpret_cast<const float4*>(bias + kc + a_k4[it]);
                v.x = fmaxf(fmaf(di, f0.x, bb.x), 0.f);
                v.y = fmaxf(fmaf(di, f0.y, bb.y), 0.f);
                v.z = fmaxf(fmaf(di, f1.x, bb.z), 0.f);
                v.w = fmaxf(fmaf(di, f1.y, bb.w), 0.f);
                if (gr >= M) v = make_float4(0.f, 0.f, 0.f, 0.f);
            } else {
                v = aregf[it];
            }
            __half2 h01 = __floats2half2_rn(v.x, v.y);
            __half2 h23 = __floats2half2_rn(v.z, v.w);
            *reinterpret_cast<uint2*>(as + a_row[it] * LD + a_k4[it]) =
                make_uint2(*reinterpret_cast<uint32_t*>(&h01), *reinterpret_cast<uint32_t*>(&h23));
        }
    };

    // ---- prologue ----
    prefetch_A(0);
    cpasync_B(0, 0);

    for (int c = 0; c < NCH; c++) {
        const int s = c & 1;
        sts_A(c * BK, s);
        asm volatile("cp.async.wait_group 0;");
        __syncthreads();
        if (c + 1 < NCH) {
            prefetch_A((c + 1) * BK);
            cpasync_B((c + 1) * BK, 1 - s);
        }

        const uint32_t s_a = s0 + s * STG;
        const uint32_t s_b = s_a + ASZ;
        #pragma unroll
        for (int kk = 0; kk < BK; kk += 16) {
            uint32_t ah[2][4];
            #pragma unroll
            for (int mt = 0; mt < 2; mt++) {
                uint32_t ar = (uint32_t)(wm * 32 + mt * 16);
                uint32_t off = ((ar + a_lrow) * LD + (uint32_t)kk + a_lk) * 2;
                ldsm_x4(ah[mt], s_a + off);
            }
            #pragma unroll
            for (int p = 0; p < NT / 2; p++) {
                uint32_t bn = (uint32_t)(wn * NW + p * 16) + b_lrow;
                uint32_t boff = (bn * LD + (uint32_t)kk + b_lk) * 2;
                uint32_t bv[4];
                ldsm_x4(bv, s_b + boff);
                #pragma unroll
                for (int q = 0; q < 2; q++) {
                    uint32_t bq[2] = {bv[2 * q], bv[2 * q + 1]};
                    #pragma unroll
                    for (int mt = 0; mt < 2; mt++)
                        mma16816h(acc[mt][2 * p + q], ah[mt], bq);
                }
            }
        }
    }

    // ---- epilogue: scale by dinv, store fp16 ----
    #pragma unroll
    for (int mt = 0; mt < 2; mt++) {
        int r0 = row0 + wm * 32 + mt * 16 + g;
        int r1 = r0 + 8;
        float s0f = (r0 < M) ? dinv[r0] : 0.0f;
        float s1f = (r1 < M) ? dinv[r1] : 0.0f;
        #pragma unroll
        for (int nt = 0; nt < NT; nt++) {
            int cc = wn * NW + nt * 8 + 2 * t;
            if (r0 < M)
                *reinterpret_cast<__half2*>(C + (long long)r0 * BN + cc) =
                    __floats2half2_rn(s0f * acc[mt][nt][0], s0f * acc[mt][nt][1]);
            if (r1 < M)
                *reinterpret_cast<__half2*>(C + (long long)r1 * BN + cc) =
                    __floats2half2_rn(s1f * acc[mt][nt][2], s1f * acc[mt][nt][3]);
        }
    }
}

// ---------------- pull layer 1 (fp16): agg1[d] = h2[d] + sum h2[src] ---------
__global__ void pull128_kernel(const __half* __restrict__ h2,
                               const int* __restrict__ row, const int* __restrict__ csr,
                               __half* __restrict__ agg, int n) {
    int gw = (blockIdx.x * blockDim.x + threadIdx.x) >> 5;
    int lane = threadIdx.x & 31;
    if (gw >= n) return;
    long long base = (long long)gw * HID_C + lane * 4;
    uint2 su = *reinterpret_cast<const uint2*>(h2 + base);
    float2 sf0 = __half22float2(*reinterpret_cast<__half2*>(&su.x));
    float2 sf1 = __half22float2(*reinterpret_cast<__half2*>(&su.y));
    float4 a = make_float4(sf0.x, sf0.y, sf1.x, sf1.y);
    int beg = row[gw], end = row[gw + 1];
    int j = beg;
    for (; j + 3 < end; j += 4) {
        int s0 = csr[j], s1 = csr[j + 1], s2 = csr[j + 2], s3 = csr[j + 3];
        uint2 u0 = *reinterpret_cast<const uint2*>(h2 + (long long)s0 * HID_C + lane * 4);
        uint2 u1 = *reinterpret_cast<const uint2*>(h2 + (long long)s1 * HID_C + lane * 4);
        uint2 u2 = *reinterpret_cast<const uint2*>(h2 + (long long)s2 * HID_C + lane * 4);
        uint2 u3 = *reinterpret_cast<const uint2*>(h2 + (long long)s3 * HID_C + lane * 4);
        float2 f;
        f = __half22float2(*reinterpret_cast<__half2*>(&u0.x)); a.x += f.x; a.y += f.y;
        f = __half22float2(*reinterpret_cast<__half2*>(&u0.y)); a.z += f.x; a.w += f.y;
        f = __half22float2(*reinterpret_cast<__half2*>(&u1.x)); a.x += f.x; a.y += f.y;
        f = __half22float2(*reinterpret_cast<__half2*>(&u1.y)); a.z += f.x; a.w += f.y;
        f = __half22float2(*reinterpret_cast<__half2*>(&u2.x)); a.x += f.x; a.y += f.y;
        f = __half22float2(*reinterpret_cast<__half2*>(&u2.y)); a.z += f.x; a.w += f.y;
        f = __half22float2(*reinterpret_cast<__half2*>(&u3.x)); a.x += f.x; a.y += f.y;
        f = __half22float2(*reinterpret_cast<__half2*>(&u3.y)); a.z += f.x; a.w += f.y;
    }
    for (; j < end; j++) {
        int s0 = csr[j];
        uint2 u0 = *reinterpret_cast<const uint2*>(h2 + (long long)s0 * HID_C + lane * 4);
        float2 f;
        f = __half22float2(*reinterpret_cast<__half2*>(&u0.x)); a.x += f.x; a.y += f.y;
        f = __half22float2(*reinterpret_cast<__half2*>(&u0.y)); a.z += f.x; a.w += f.y;
    }
    __half2 o0 = __floats2half2_rn(a.x, a.y);
    __half2 o1 = __floats2half2_rn(a.z, a.w);
    *reinterpret_cast<uint2*>(agg + base) =
        make_uint2(*reinterpret_cast<uint32_t*>(&o0), *reinterpret_cast<uint32_t*>(&o1));
}

// ---------------- pull layer 2 (fp16) + degi/desc reset tail -----------------
__global__ void pull64_kernel(const __half* __restrict__ z2,
                              const int* __restrict__ row, const int* __restrict__ csr,
                              const float* __restrict__ dinv, const float* __restrict__ b2,
                              float* __restrict__ out, int n,
                              int pull_blocks, int* __restrict__ degi,
                              unsigned long long* __restrict__ desc) {
    if ((int)blockIdx.x >= pull_blocks) {
        int base = ((int)blockIdx.x - pull_blocks) * 2048 + threadIdx.x * 8;
        #pragma unroll
        for (int k = 0; k < 8; k++) {
            int i = base + k;
            if (i < NN) degi[i] = 0;
            else if (i - NN < NB) desc[i - NN] = 0ULL;
        }
        return;
    }
    int gw = (blockIdx.x * blockDim.x + threadIdx.x) >> 5;
    int lane = threadIdx.x & 31;
    if (gw >= n) return;
    long long base = (long long)gw * OUT_C + lane * 2;
    float2 a = __half22float2(*reinterpret_cast<const __half2*>(z2 + base));
    int beg = row[gw], end = row[gw + 1];
    int j = beg;
    for (; j + 3 < end; j += 4) {
        int s0 = csr[j], s1 = csr[j + 1], s2 = csr[j + 2], s3 = csr[j + 3];
        float2 f0 = __half22float2(*reinterpret_cast<const __half2*>(z2 + (long long)s0 * OUT_C + lane * 2));
        float2 f1 = __half22float2(*reinterpret_cast<const __half2*>(z2 + (long long)s1 * OUT_C + lane * 2));
        float2 f2 = __half22float2(*reinterpret_cast<const __half2*>(z2 + (long long)s2 * OUT_C + lane * 2));
        float2 f3 = __half22float2(*reinterpret_cast<const __half2*>(z2 + (long long)s3 * OUT_C + lane * 2));
        a.x += (f0.x + f1.x) + (f2.x + f3.x);
        a.y += (f0.y + f1.y) + (f2.y + f3.y);
    }
    for (; j < end; j++) {
        int s0 = csr[j];
        float2 f0 = __half22float2(*reinterpret_cast<const __half2*>(z2 + (long long)s0 * OUT_C + lane * 2));
        a.x += f0.x; a.y += f0.y;
    }
    float di = dinv[gw];
    float2 bb = *reinterpret_cast<const float2*>(b2 + lane * 2);
    *reinterpret_cast<float2*>(out + base) =
        make_float2(fmaf(di, a.x, bb.x), fmaf(di, a.y, bb.y));
}

// ---------------- launch ----------------
extern "C" void kernel_launch(void* const* d_in, const int* in_sizes, int n_in,
                              void* d_out, int out_size) {
    const float* x  = (const float*)d_in[0];
    const int*   ei = (const int*)  d_in[1];
    const float* W1 = (const float*)d_in[2];
    const float* b1 = (const float*)d_in[3];
    const float* W2 = (const float*)d_in[4];
    const float* b2 = (const float*)d_in[5];
    float* out = (float*)d_out;

    const int E = in_sizes[1] / 2;
    const int* src = ei;
    const int* dst = ei + E;

    float *dinv;
    int *degi, *row, *cur, *csr;
    unsigned long long* desc;
    __half *h2, *agg1, *z2, *w1h, *w2h;
    cudaGetSymbolAddress((void**)&dinv, g_dinv);
    cudaGetSymbolAddress((void**)&degi, g_degi);
    cudaGetSymbolAddress((void**)&row,  g_row);
    cudaGetSymbolAddress((void**)&cur,  g_cur);
    cudaGetSymbolAddress((void**)&desc, g_desc);
    cudaGetSymbolAddress((void**)&csr,  g_csr);
    cudaGetSymbolAddress((void**)&h2,   g_h2);
    cudaGetSymbolAddress((void**)&agg1, g_agg1);
    cudaGetSymbolAddress((void**)&z2,   g_z2);
    cudaGetSymbolAddress((void**)&w1h,  g_w1h);
    cudaGetSymbolAddress((void**)&w2h,  g_w2h);

    const int LD = 40;
    const int SMEM1 = 2 * (64 * LD * 2 + 128 * LD * 2);   // 30720 B
    const int SMEM2 = 2 * (64 * LD * 2 + 64 * LD * 2);    // 20480 B
    cudaFuncSetAttribute(mma_gemm<HID_C, IN_C, false>,
                         cudaFuncAttributeMaxDynamicSharedMemorySize, SMEM1);
    cudaFuncSetAttribute(mma_gemm<OUT_C, HID_C, true>,
                         cudaFuncAttributeMaxDynamicSharedMemorySize, SMEM2);

    // 1) prep: vectorized degree histogram + W fp16 conversion
    {
        int total = E / 4 + IN_C * HID_C + HID_C * OUT_C;
        prep_count_kernel<<<(total + 255) / 256, 256>>>(dst, E, W1, W2, degi, w1h, w2h);
    }
    // 2) single-pass scan -> row/cur + dinv
    scan_kernel<<<NB, 256>>>(degi, desc, row, cur, dinv, NN);
    // 3) CSR slot scatter (4 edges/thread)
    slot_scatter_kernel<<<(E / 4 + 255) / 256, 256>>>(src, dst, cur, csr, E);

    // 4) GEMM1 (pipelined fp16x1 HMMA, BM=64, 3 CTAs/SM): h2 = fp16(dinv*(x@W1))
    mma_gemm<HID_C, IN_C, false><<<(NN + 63) / 64, 256, SMEM1>>>(
        x, w1h, h2, dinv, nullptr, NN);
    // 5) pull layer 1
    pull128_kernel<<<(NN * 32 + 255) / 256, 256>>>(h2, row, csr, agg1, NN);
    // 6) GEMM2: z2 = fp16( dinv * (relu(b1 + dinv*agg1) @ W2) )
    mma_gemm<OUT_C, HID_C, true><<<(NN + 63) / 64, 256, SMEM2>>>(
        agg1, w2h, z2, dinv, b1, NN);
    // 7) pull layer 2 + bias; tail blocks reset degi/desc
    {
        const int PULL_BLOCKS = (NN * 32 + 255) / 256;
        const int ZERO_BLOCKS = (NN + NB + 2047) / 2048;
        pull64_kernel<<<PULL_BLOCKS + ZERO_BLOCKS, 256>>>(
            z2, row, csr, dinv, b2, out, NN, PULL_BLOCKS, degi, desc);
    }
}